// round 2
// baseline (speedup 1.0000x reference)
#include <cuda_runtime.h>
#include <math.h>

// Problem shape (fixed by setup_inputs): x [T=4, B=32, C=256, H=32, W=32]
#define Tn 4
#define Bn 32
#define Cn 256
#define Hn 32
#define Wn 32
#define Pn 1024                 // H*W
#define CCHUNKS 8
#define CPER (Cn / CCHUNKS)     // 32 channels per chunk
#define TSTR ((size_t)Bn * Cn * Pn)   // t-stride in floats

// Scratch: partial[sel][chunk][b][p], sel 0 = csum, 1 = ssq.  2*8*32*1024 floats = 2 MB
__device__ float g_partial[2 * CCHUNKS * Bn * Pn];

// ---------------------------------------------------------------------------
// Kernel A: reduce over T (mean) and a C-chunk (sum of mean, sum of mean^2).
// One thread handles 4 consecutive pixels via float4 (coalesced).
// ---------------------------------------------------------------------------
__global__ void __launch_bounds__(256) reduce_kernel(const float* __restrict__ x) {
    const int b     = blockIdx.x;
    const int chunk = blockIdx.y;
    const int tid   = threadIdx.x;            // 0..255, each owns pixels [4*tid, 4*tid+3]

    const float4* base =
        (const float4*)(x + ((size_t)b * Cn + (size_t)chunk * CPER) * Pn) + tid;

    float4 cs = make_float4(0.f, 0.f, 0.f, 0.f);
    float4 sq = make_float4(0.f, 0.f, 0.f, 0.f);

    const size_t t4 = TSTR / 4;               // t-stride in float4s

#pragma unroll 4
    for (int c = 0; c < CPER; ++c) {
        const float4* p = base + (size_t)c * (Pn / 4);
        float4 a0 = __ldg(p);
        float4 a1 = __ldg(p + t4);
        float4 a2 = __ldg(p + 2 * t4);
        float4 a3 = __ldg(p + 3 * t4);

        float4 m;
        m.x = (a0.x + a1.x + a2.x + a3.x) * 0.25f;
        m.y = (a0.y + a1.y + a2.y + a3.y) * 0.25f;
        m.z = (a0.z + a1.z + a2.z + a3.z) * 0.25f;
        m.w = (a0.w + a1.w + a2.w + a3.w) * 0.25f;

        cs.x += m.x; cs.y += m.y; cs.z += m.z; cs.w += m.w;
        sq.x += m.x * m.x; sq.y += m.y * m.y; sq.z += m.z * m.z; sq.w += m.w * m.w;
    }

    float4* outp = (float4*)g_partial;
    outp[(((size_t)0 * CCHUNKS + chunk) * Bn + b) * (Pn / 4) + tid] = cs;
    outp[(((size_t)1 * CCHUNKS + chunk) * Bn + b) * (Pn / 4) + tid] = sq;
}

// ---------------------------------------------------------------------------
// Kernel B: per batch — combine partials, 3x3 box filter (zero-padded) on
// csum, cosine-similarity collapse, mask, softmax over the 1024 pixels.
// ---------------------------------------------------------------------------
__global__ void __launch_bounds__(1024) final_kernel(const int* __restrict__ mask,
                                                     float* __restrict__ out) {
    const int b   = blockIdx.x;
    const int tid = threadIdx.x;              // 0..1023 = pixel index
    const int h   = tid >> 5;
    const int w   = tid & 31;

    float cs = 0.f, sq = 0.f;
#pragma unroll
    for (int k = 0; k < CCHUNKS; ++k) {
        cs += g_partial[(((size_t)0 * CCHUNKS + k) * Bn + b) * Pn + tid];
        sq += g_partial[(((size_t)1 * CCHUNKS + k) * Bn + b) * Pn + tid];
    }

    // 3x3 same-padded box sum of csum over the 32x32 spatial grid.
    __shared__ float s_cs[34 * 34];
    for (int i = tid; i < 34 * 34; i += 1024) s_cs[i] = 0.f;
    __syncthreads();
    s_cs[(h + 1) * 34 + (w + 1)] = cs;
    __syncthreads();

    float box = 0.f;
#pragma unroll
    for (int dh = 0; dh < 3; ++dh)
#pragma unroll
        for (int dw = 0; dw < 3; ++dw)
            box += s_cs[(h + dh) * 34 + (w + dw)];

    const float lm = box * (1.f / 9.f);
    const float nx = sqrtf(sq);               // ||xm||_2 over channels
    const float ny = 16.f * fabsf(lm);        // sqrt(C)=16
    const float sim = (lm * cs) / (fmaxf(nx, 1e-6f) * fmaxf(ny, 1e-6f));

    const bool dropped = mask[(size_t)b * Pn + tid] != 0;
    const float score = dropped ? -INFINITY : -sim;

    // ---- block softmax over 1024 entries ----
    __shared__ float red[32];
    const int lane = tid & 31;
    const int wid  = tid >> 5;

    float m = score;
#pragma unroll
    for (int o = 16; o; o >>= 1) m = fmaxf(m, __shfl_xor_sync(0xFFFFFFFFu, m, o));
    if (lane == 0) red[wid] = m;
    __syncthreads();
    float gmax = -INFINITY;
#pragma unroll
    for (int i = 0; i < 32; ++i) gmax = fmaxf(gmax, red[i]);
    __syncthreads();

    const float e = __expf(score - gmax);     // -inf -> 0
    float s = e;
#pragma unroll
    for (int o = 16; o; o >>= 1) s += __shfl_xor_sync(0xFFFFFFFFu, s, o);
    if (lane == 0) red[wid] = s;
    __syncthreads();
    float gsum = 0.f;
#pragma unroll
    for (int i = 0; i < 32; ++i) gsum += red[i];

    out[(size_t)b * Pn + tid] = e / gsum;
}

// ---------------------------------------------------------------------------
extern "C" void kernel_launch(void* const* d_in, const int* in_sizes, int n_in,
                              void* d_out, int out_size) {
    const float* x = (const float*)d_in[0];
    const int* mask = (const int*)d_in[1];
    float* out = (float*)d_out;

    dim3 gridA(Bn, CCHUNKS);
    reduce_kernel<<<gridA, 256>>>(x);
    final_kernel<<<Bn, 1024>>>(mask, out);
}

// round 3
// speedup vs baseline: 1.0328x; 1.0328x over previous
#include <cuda_runtime.h>
#include <math.h>

// Problem shape (fixed by setup_inputs): x [T=4, B=32, C=256, H=32, W=32]
#define Tn 4
#define Bn 32
#define Cn 256
#define Hn 32
#define Wn 32
#define Pn 1024                 // H*W
#define CCHUNKS 8
#define CPER (Cn / CCHUNKS)     // 32 channels per chunk
#define TSTR ((size_t)Bn * Cn * Pn)   // t-stride in floats

// Scratch: partial[sel][chunk][b][p], sel 0 = csum, 1 = ssq.  2*8*32*1024 floats = 2 MB
__device__ float g_partial[2 * CCHUNKS * Bn * Pn];

// ---------------------------------------------------------------------------
// Kernel A: reduce over T (mean) and a C-chunk (sum of mean, sum of mean^2).
// One thread handles 4 consecutive pixels via float4 (coalesced).
// Deep unroll -> ~32 outstanding 16B loads per thread to hide DRAM latency.
// ---------------------------------------------------------------------------
__global__ void __launch_bounds__(256) reduce_kernel(const float* __restrict__ x) {
    const int b     = blockIdx.x;
    const int chunk = blockIdx.y;
    const int tid   = threadIdx.x;            // 0..255, each owns pixels [4*tid, 4*tid+3]

    const float4* base =
        (const float4*)(x + ((size_t)b * Cn + (size_t)chunk * CPER) * Pn) + tid;

    float4 cs = make_float4(0.f, 0.f, 0.f, 0.f);
    float4 sq = make_float4(0.f, 0.f, 0.f, 0.f);

    const size_t t4 = TSTR / 4;               // t-stride in float4s

#pragma unroll 8
    for (int c = 0; c < CPER; ++c) {
        const float4* p = base + (size_t)c * (Pn / 4);
        float4 a0 = __ldg(p);
        float4 a1 = __ldg(p + t4);
        float4 a2 = __ldg(p + 2 * t4);
        float4 a3 = __ldg(p + 3 * t4);

        float4 m;
        m.x = (a0.x + a1.x + a2.x + a3.x) * 0.25f;
        m.y = (a0.y + a1.y + a2.y + a3.y) * 0.25f;
        m.z = (a0.z + a1.z + a2.z + a3.z) * 0.25f;
        m.w = (a0.w + a1.w + a2.w + a3.w) * 0.25f;

        cs.x += m.x; cs.y += m.y; cs.z += m.z; cs.w += m.w;
        sq.x += m.x * m.x; sq.y += m.y * m.y; sq.z += m.z * m.z; sq.w += m.w * m.w;
    }

    float4* outp = (float4*)g_partial;
    outp[(((size_t)0 * CCHUNKS + chunk) * Bn + b) * (Pn / 4) + tid] = cs;
    outp[(((size_t)1 * CCHUNKS + chunk) * Bn + b) * (Pn / 4) + tid] = sq;
}

// ---------------------------------------------------------------------------
// Kernel B: per batch — combine partials, 3x3 box filter (zero-padded) on
// csum, cosine-similarity collapse, mask, softmax over the 1024 pixels.
// ---------------------------------------------------------------------------
__global__ void __launch_bounds__(1024) final_kernel(const int* __restrict__ mask,
                                                     float* __restrict__ out) {
    const int b   = blockIdx.x;
    const int tid = threadIdx.x;              // 0..1023 = pixel index
    const int h   = tid >> 5;
    const int w   = tid & 31;
    const int lane = tid & 31;
    const int wid  = tid >> 5;

    // Issue all 16 partial loads + the mask load up front (overlapped).
    float pcs[CCHUNKS], psq[CCHUNKS];
#pragma unroll
    for (int k = 0; k < CCHUNKS; ++k) {
        pcs[k] = __ldg(&g_partial[(((size_t)0 * CCHUNKS + k) * Bn + b) * Pn + tid]);
        psq[k] = __ldg(&g_partial[(((size_t)1 * CCHUNKS + k) * Bn + b) * Pn + tid]);
    }
    const int mraw = __ldg(&mask[(size_t)b * Pn + tid]);

    float cs = 0.f, sq = 0.f;
#pragma unroll
    for (int k = 0; k < CCHUNKS; ++k) { cs += pcs[k]; sq += psq[k]; }

    // 3x3 same-padded box sum of csum over the 32x32 spatial grid.
    __shared__ float s_cs[34 * 34];
    for (int i = tid; i < 34 * 34; i += 1024) s_cs[i] = 0.f;
    __syncthreads();
    s_cs[(h + 1) * 34 + (w + 1)] = cs;
    __syncthreads();

    float box = 0.f;
#pragma unroll
    for (int dh = 0; dh < 3; ++dh)
#pragma unroll
        for (int dw = 0; dw < 3; ++dw)
            box += s_cs[(h + dh) * 34 + (w + dw)];

    const float lm = box * (1.f / 9.f);
    const float nx = sqrtf(sq);               // ||xm||_2 over channels
    const float ny = 16.f * fabsf(lm);        // sqrt(C)=16
    const float sim = (lm * cs) / (fmaxf(nx, 1e-6f) * fmaxf(ny, 1e-6f));

    const float score = mraw ? -INFINITY : -sim;

    // ---- block softmax over 1024 entries (two-level shuffle reduce) ----
    __shared__ float red[32];
    __shared__ float bc[2];                   // [0]=max, [1]=sum

    float m = score;
#pragma unroll
    for (int o = 16; o; o >>= 1) m = fmaxf(m, __shfl_xor_sync(0xFFFFFFFFu, m, o));
    if (lane == 0) red[wid] = m;
    __syncthreads();
    if (wid == 0) {
        float v = red[lane];
#pragma unroll
        for (int o = 16; o; o >>= 1) v = fmaxf(v, __shfl_xor_sync(0xFFFFFFFFu, v, o));
        if (lane == 0) bc[0] = v;
    }
    __syncthreads();
    const float gmax = bc[0];

    const float e = __expf(score - gmax);     // -inf -> 0
    float s = e;
#pragma unroll
    for (int o = 16; o; o >>= 1) s += __shfl_xor_sync(0xFFFFFFFFu, s, o);
    if (lane == 0) red[wid] = s;
    __syncthreads();
    if (wid == 0) {
        float v = red[lane];
#pragma unroll
        for (int o = 16; o; o >>= 1) v += __shfl_xor_sync(0xFFFFFFFFu, v, o);
        if (lane == 0) bc[1] = v;
    }
    __syncthreads();

    out[(size_t)b * Pn + tid] = e * __frcp_rn(bc[1]);
}

// ---------------------------------------------------------------------------
extern "C" void kernel_launch(void* const* d_in, const int* in_sizes, int n_in,
                              void* d_out, int out_size) {
    const float* x = (const float*)d_in[0];
    const int* mask = (const int*)d_in[1];
    float* out = (float*)d_out;

    dim3 gridA(Bn, CCHUNKS);
    reduce_kernel<<<gridA, 256>>>(x);
    final_kernel<<<Bn, 1024>>>(mask, out);
}

// round 4
// speedup vs baseline: 1.1313x; 1.0954x over previous
#include <cuda_runtime.h>
#include <math.h>

// Problem shape (fixed): x [T=4, B=32, C=256, H=32, W=32]
#define Tn 4
#define Bn 32
#define Cn 256
#define Pn 1024
#define NSL 1024            // slices = B * 32 chunks (8 channels each)
#define NBLK 148            // persistent grid = one CTA per SM

// partial4[sel][slice][pg] : sel 0 = csum, 1 = ssq. 2*1024*256 float4 = 8 MB (L2-resident)
__device__ float4 g_partial4[2 * NSL * 256];

__device__ __forceinline__ float4 f4add(float4 a, float4 b) {
    return make_float4(a.x + b.x, a.y + b.y, a.z + b.z, a.w + b.w);
}
__device__ __forceinline__ float4 f4fma(float4 a, float4 b, float4 c) {
    return make_float4(fmaf(a.x, b.x, c.x), fmaf(a.y, b.y, c.y),
                       fmaf(a.z, b.z, c.z), fmaf(a.w, b.w, c.w));
}

// ---------------------------------------------------------------------------
// Persistent reduce: slice = (b, chunk of 8 channels). 1024 threads:
//   pg = tid&255 (4 pixels via float4), csub = tid>>8 (2 channels).
// Software pipeline: next slice's 8 LDG.128 issued before the barrier phase.
// ---------------------------------------------------------------------------
__global__ void __launch_bounds__(1024, 1) reduce_kernel(const float* __restrict__ xf) {
    const float4* __restrict__ X = (const float4*)xf;
    const int tid  = threadIdx.x;
    const int pg   = tid & 255;
    const int csub = tid >> 8;

    __shared__ float4 scs[3][256];
    __shared__ float4 ssq[3][256];

    const size_t tstr = (size_t)Bn * Cn * 256;   // t-plane stride in float4

    int sl = blockIdx.x;
    float4 r[8];
    {
        const int b = sl >> 5, ch = sl & 31;
        const int c = ch * 8 + csub * 2;
        const size_t base = ((size_t)b * Cn + c) * 256 + pg;
#pragma unroll
        for (int t = 0; t < 4; ++t) {
            r[t]     = __ldg(X + base + (size_t)t * tstr);
            r[4 + t] = __ldg(X + base + 256 + (size_t)t * tstr);
        }
    }

    for (;;) {
        // reduce current slice's 8 loads: mean over t, then cs / ssq
        float4 m0, m1;
        m0.x = (r[0].x + r[1].x + r[2].x + r[3].x) * 0.25f;
        m0.y = (r[0].y + r[1].y + r[2].y + r[3].y) * 0.25f;
        m0.z = (r[0].z + r[1].z + r[2].z + r[3].z) * 0.25f;
        m0.w = (r[0].w + r[1].w + r[2].w + r[3].w) * 0.25f;
        m1.x = (r[4].x + r[5].x + r[6].x + r[7].x) * 0.25f;
        m1.y = (r[4].y + r[5].y + r[6].y + r[7].y) * 0.25f;
        m1.z = (r[4].z + r[5].z + r[6].z + r[7].z) * 0.25f;
        m1.w = (r[4].w + r[5].w + r[6].w + r[7].w) * 0.25f;

        float4 cs4 = f4add(m0, m1);
        float4 sq4 = f4fma(m1, m1, f4fma(m0, m0, make_float4(0.f, 0.f, 0.f, 0.f)));

        const int cur  = sl;
        const int nxt  = sl + NBLK;
        const bool more = (nxt < NSL);

        if (more) {   // issue next slice's loads NOW; they fly across the barriers
            const int b = nxt >> 5, ch = nxt & 31;
            const int c = ch * 8 + csub * 2;
            const size_t base = ((size_t)b * Cn + c) * 256 + pg;
#pragma unroll
            for (int t = 0; t < 4; ++t) {
                r[t]     = __ldg(X + base + (size_t)t * tstr);
                r[4 + t] = __ldg(X + base + 256 + (size_t)t * tstr);
            }
        }

        if (csub) { scs[csub - 1][pg] = cs4; ssq[csub - 1][pg] = sq4; }
        __syncthreads();
        if (!csub) {
            cs4 = f4add(f4add(cs4, scs[0][pg]), f4add(scs[1][pg], scs[2][pg]));
            sq4 = f4add(f4add(sq4, ssq[0][pg]), f4add(ssq[1][pg], ssq[2][pg]));
            g_partial4[(size_t)cur * 256 + pg] = cs4;
            g_partial4[(size_t)(NSL + cur) * 256 + pg] = sq4;
        }
        if (!more) break;
        __syncthreads();      // protect smem reuse next iteration
        sl = nxt;
    }
}

// ---------------------------------------------------------------------------
// Final: per batch — combine 32 chunk-partials (float4, L2), transpose via
// smem to per-pixel, 3x3 zero-padded box filter, cosine collapse, softmax.
// ---------------------------------------------------------------------------
__global__ void __launch_bounds__(1024) final_kernel(const int* __restrict__ mask,
                                                     float* __restrict__ out) {
    const int b    = blockIdx.x;
    const int tid  = threadIdx.x;           // pixel index for phase 2
    const int pg   = tid & 255;
    const int csub = tid >> 8;
    const int h    = tid >> 5;
    const int w    = tid & 31;
    const int lane = tid & 31;
    const int wid  = tid >> 5;

    const int mraw = __ldg(&mask[(size_t)b * Pn + tid]);

    // phase 1: each csub sums 8 chunks (float4)
    float4 cs4 = make_float4(0.f, 0.f, 0.f, 0.f);
    float4 sq4 = make_float4(0.f, 0.f, 0.f, 0.f);
#pragma unroll
    for (int j = 0; j < 8; ++j) {
        const int sl = b * 32 + csub * 8 + j;
        cs4 = f4add(cs4, __ldg(&g_partial4[(size_t)sl * 256 + pg]));
        sq4 = f4add(sq4, __ldg(&g_partial4[(size_t)(NSL + sl) * 256 + pg]));
    }

    __shared__ float4 tcs[4][256];
    __shared__ float4 tsq[4][256];
    tcs[csub][pg] = cs4;
    tsq[csub][pg] = sq4;
    __syncthreads();

    // phase 2: per-pixel totals
    const float* fcs = (const float*)tcs;
    const float* fsq = (const float*)tsq;
    float cs = 0.f, sq = 0.f;
#pragma unroll
    for (int c2 = 0; c2 < 4; ++c2) {
        cs += fcs[c2 * 1024 + tid];
        sq += fsq[c2 * 1024 + tid];
    }

    // 3x3 zero-padded box sum over 32x32
    __shared__ float s_cs[34 * 34];
    for (int i = tid; i < 34 * 34; i += 1024) s_cs[i] = 0.f;
    __syncthreads();
    s_cs[(h + 1) * 34 + (w + 1)] = cs;
    __syncthreads();

    float box = 0.f;
#pragma unroll
    for (int dh = 0; dh < 3; ++dh)
#pragma unroll
        for (int dw = 0; dw < 3; ++dw)
            box += s_cs[(h + dh) * 34 + (w + dw)];

    const float lm  = box * (1.f / 9.f);
    const float nx  = sqrtf(sq);
    const float ny  = 16.f * fabsf(lm);       // sqrt(C)=16
    const float sim = (lm * cs) / (fmaxf(nx, 1e-6f) * fmaxf(ny, 1e-6f));
    const float score = mraw ? -INFINITY : -sim;

    // block softmax over 1024 entries
    __shared__ float red[32];
    __shared__ float bc[2];

    float m = score;
#pragma unroll
    for (int o = 16; o; o >>= 1) m = fmaxf(m, __shfl_xor_sync(0xFFFFFFFFu, m, o));
    if (lane == 0) red[wid] = m;
    __syncthreads();
    if (wid == 0) {
        float v = red[lane];
#pragma unroll
        for (int o = 16; o; o >>= 1) v = fmaxf(v, __shfl_xor_sync(0xFFFFFFFFu, v, o));
        if (lane == 0) bc[0] = v;
    }
    __syncthreads();
    const float gmax = bc[0];

    const float e = __expf(score - gmax);
    float s = e;
#pragma unroll
    for (int o = 16; o; o >>= 1) s += __shfl_xor_sync(0xFFFFFFFFu, s, o);
    if (lane == 0) red[wid] = s;
    __syncthreads();
    if (wid == 0) {
        float v = red[lane];
#pragma unroll
        for (int o = 16; o; o >>= 1) v += __shfl_xor_sync(0xFFFFFFFFu, v, o);
        if (lane == 0) bc[1] = v;
    }
    __syncthreads();

    out[(size_t)b * Pn + tid] = e * __frcp_rn(bc[1]);
}

// ---------------------------------------------------------------------------
extern "C" void kernel_launch(void* const* d_in, const int* in_sizes, int n_in,
                              void* d_out, int out_size) {
    const float* x = (const float*)d_in[0];
    const int* mask = (const int*)d_in[1];
    float* out = (float*)d_out;

    reduce_kernel<<<NBLK, 1024>>>(x);
    final_kernel<<<Bn, 1024>>>(mask, out);
}